// round 15
// baseline (speedup 1.0000x reference)
#include <cuda_runtime.h>
#include <cuda_fp16.h>
#include <cstdint>
#include <math.h>

// Problem dims
#define B_    16
#define CIN   512
#define COUT  512
#define H_    64
#define W_    64
#define HW    4096
#define SDIM  32
#define OH    128
#define OW    128
#define EPS   1e-8f

// Scratch
__device__ uint32_t g_wh[(size_t)B_ * COUT * CIN / 2];   // fp16 A-fragment-ordered weights (8 MB)
__device__ uint4    g_xf[(size_t)B_ * 16 * 512 * 32];    // fp16 B-fragment-ordered x (67 MB)
__device__ __half   g_yh[(size_t)B_ * COUT * HW];        // conv output, fp16 (67 MB)

// ---------------------------------------------------------------------------
// Kernel A (merged prep): blocks [0, 16384) do xcvt; blocks [16384, 16512)
// do wprep. Independent outputs (g_xf vs g_wh) -> full concurrency.
// ---------------------------------------------------------------------------
__global__ __launch_bounds__(256) void prep_kernel(
    const float* __restrict__ x,
    const float* __restrict__ style,
    const float* __restrict__ conv_w,
    const float* __restrict__ mod_w,
    const float* __restrict__ mod_b)
{
    __shared__ float s_sh[CIN];
    __shared__ float dm_sh[64];

    unsigned blk = blockIdx.x;
    int tid = threadIdx.x;

    if (blk < 16384u) {
        // ---- xcvt: x -> B-fragment order (R10 direct version) ----
        unsigned seg = blk & 63u;
        unsigned c   = (blk >> 6) & 15u;
        unsigned b   = blk >> 10;

        unsigned t  = seg * 256u + tid;
        unsigned tg = t & 3u;
        unsigned p  = t >> 2;

        const float* xb = x + (size_t)b * CIN * HW + p;
        unsigned rbase = c * 32 + 2 * tg;

        uint4 u;
        {
            float lo = __ldg(xb + (size_t)(rbase + 0) * HW);
            float hi = __ldg(xb + (size_t)(rbase + 1) * HW);
            __half2 h = __floats2half2_rn(lo, hi); u.x = *(uint32_t*)&h;
        }
        {
            float lo = __ldg(xb + (size_t)(rbase + 8) * HW);
            float hi = __ldg(xb + (size_t)(rbase + 9) * HW);
            __half2 h = __floats2half2_rn(lo, hi); u.y = *(uint32_t*)&h;
        }
        {
            float lo = __ldg(xb + (size_t)(rbase + 16) * HW);
            float hi = __ldg(xb + (size_t)(rbase + 17) * HW);
            __half2 h = __floats2half2_rn(lo, hi); u.z = *(uint32_t*)&h;
        }
        {
            float lo = __ldg(xb + (size_t)(rbase + 24) * HW);
            float hi = __ldg(xb + (size_t)(rbase + 25) * HW);
            __half2 h = __floats2half2_rn(lo, hi); u.w = *(uint32_t*)&h;
        }

        unsigned n8 = p >> 3;
        unsigned lane_out = (p & 7u) * 4u + tg;
        g_xf[((size_t)(b * 16 + c) * 512 + n8) * 32 + lane_out] = u;
        return;
    }

    // ---- wprep: modulation + demod + fragment-ordered weights ----
    unsigned w = blk - 16384u;          // 0..127
    int ot = w & 3;                     // 0..3
    int gh = (w >> 2) & 1;              // 0..1
    int b  = w >> 3;                    // 0..15

    int wid = tid >> 5, lane = tid & 31;
    int gid = lane >> 2, tg = lane & 3;

    const float* st = style + b * SDIM;
#pragma unroll
    for (int rep = 0; rep < 2; rep++) {
        int i = tid + rep * 256;
        float acc = mod_b[i];
        const float* mw = mod_w + i * SDIM;
#pragma unroll
        for (int k = 0; k < SDIM; k++) acc += st[k] * mw[k];
        s_sh[i] = acc;
    }
    __syncthreads();

    int obase = ot * 128 + gh * 64;
#pragma unroll
    for (int cc = 0; cc < 8; cc++) {
        int ol = wid * 8 + cc;
        const float* cw = conv_w + (size_t)(obase + ol) * CIN;
        float sum = 0.f;
#pragma unroll
        for (int it = 0; it < 4; it++) {
            int k4 = lane + it * 32;
            float4 v = __ldg((const float4*)cw + k4);
            int k = k4 * 4;
            float t0 = v.x * s_sh[k], t1 = v.y * s_sh[k + 1];
            float t2 = v.z * s_sh[k + 2], t3 = v.w * s_sh[k + 3];
            sum += t0 * t0 + t1 * t1 + t2 * t2 + t3 * t3;
        }
#pragma unroll
        for (int off = 16; off; off >>= 1)
            sum += __shfl_xor_sync(0xFFFFFFFFu, sum, off);
        if (lane == 0) dm_sh[ol] = rsqrtf(sum + EPS);
    }
    __syncthreads();

    int s  = wid >> 2;
    int mt = wid & 3;
    int fgrp = gh * 8 + wid;
    int o0l = mt * 16 + gid;
    int o1l = o0l + 8;
    int o0 = obase + o0l, o1 = obase + o1l;
    float d0 = dm_sh[o0l];
    float d1 = dm_sh[o1l];

    uint32_t* cb0 = g_wh + ((size_t)((b * 4 + ot) * 16)) * 2048 + fgrp * 128 + lane * 4;
    const float* w0row = conv_w + (size_t)o0 * CIN;
    const float* w1row = conv_w + (size_t)o1 * CIN;

#pragma unroll 4
    for (int c = 0; c < 16; c++) {
        int k0 = c * 32 + s * 16 + tg * 2;
        float s00 = s_sh[k0],     s01 = s_sh[k0 + 1];
        float s08 = s_sh[k0 + 8], s09 = s_sh[k0 + 9];

        float2 w0a = __ldg((const float2*)(w0row + k0));
        float2 w0b = __ldg((const float2*)(w0row + k0 + 8));
        float2 w1a = __ldg((const float2*)(w1row + k0));
        float2 w1b = __ldg((const float2*)(w1row + k0 + 8));

        __half2 h0 = __floats2half2_rn(w0a.x * s00 * d0, w0a.y * s01 * d0);
        __half2 h1 = __floats2half2_rn(w1a.x * s00 * d1, w1a.y * s01 * d1);
        __half2 h2 = __floats2half2_rn(w0b.x * s08 * d0, w0b.y * s09 * d0);
        __half2 h3 = __floats2half2_rn(w1b.x * s08 * d1, w1b.y * s09 * d1);

        uint4 u;
        u.x = *(uint32_t*)&h0; u.y = *(uint32_t*)&h1;
        u.z = *(uint32_t*)&h2; u.w = *(uint32_t*)&h3;
        *(uint4*)(cb0 + (size_t)c * 2048) = u;
    }
}

// ---------------------------------------------------------------------------
// Kernel B: batched GEMM, mma.sync.m16n8k16.f16.
// 5-stage cp.async (measured optimum), one sync per chunk:
//   wait 3 -> sync -> bv LDS -> issue(ch+4) -> compute(ch).
// ---------------------------------------------------------------------------
#define A_U32 2048
#define B_U32 2048
#define STAGE_U32 (A_U32 + B_U32)
#define NSTAGE 5
#define SM_GEMM_BYTES (NSTAGE * STAGE_U32 * 4)   // 81920

__device__ __forceinline__ uint32_t smem_u32(const void* p) {
    uint32_t a;
    asm("{ .reg .u64 t; cvta.to.shared.u64 t, %1; cvt.u32.u64 %0, t; }" : "=r"(a) : "l"(p));
    return a;
}

__global__ __launch_bounds__(256, 2) void gemm_mma(void)
{
    extern __shared__ uint32_t smu[];

    int tid = threadIdx.x;
    int wid = tid >> 5, lane = tid & 31;
    int gid = lane >> 2, tg = lane & 3;
    int b = blockIdx.z, oTile = blockIdx.y * 128, pTile = blockIdx.x * 128;
    int g = wid >> 2, wn = (wid & 3) * 32, wnb = (wid & 3) * 4;

    const uint32_t* aglob = g_wh + ((size_t)((b * 4 + blockIdx.y) * 16)) * 2048;
    const uint4*    bglob = g_xf + (size_t)b * 262144 + (size_t)(pTile >> 3) * 32;

    uint32_t sm_u = smem_u32(smu);

    auto issue = [&](int ch) {
        int buf = ch % NSTAGE;
        uint32_t stage = sm_u + buf * STAGE_U32 * 4;
        const uint32_t* as_ = aglob + ch * 2048 + tid * 8;
        uint32_t ad = stage + tid * 32;
        asm volatile("cp.async.cg.shared.global [%0], [%1], 16;" :: "r"(ad),      "l"(as_)     : "memory");
        asm volatile("cp.async.cg.shared.global [%0], [%1], 16;" :: "r"(ad + 16), "l"(as_ + 4) : "memory");
        const uint4* bs_ = bglob + (size_t)ch * 16384 + tid * 2;
        uint32_t bd = stage + A_U32 * 4 + tid * 32;
        asm volatile("cp.async.cg.shared.global [%0], [%1], 16;" :: "r"(bd),      "l"(bs_)     : "memory");
        asm volatile("cp.async.cg.shared.global [%0], [%1], 16;" :: "r"(bd + 16), "l"(bs_ + 1) : "memory");
        asm volatile("cp.async.commit_group;" ::: "memory");
    };

    float c[4][4][4];
#pragma unroll
    for (int mt = 0; mt < 4; mt++)
#pragma unroll
        for (int nt = 0; nt < 4; nt++)
#pragma unroll
            for (int q = 0; q < 4; q++) c[mt][nt][q] = 0.f;

    issue(0); issue(1); issue(2); issue(3);

    const int NCH = CIN / 32;   // 16
    for (int ch = 0; ch < NCH; ch++) {
        if (ch + 3 < NCH) {
            asm volatile("cp.async.wait_group 3;" ::: "memory");
        } else if (ch + 2 < NCH) {
            asm volatile("cp.async.wait_group 2;" ::: "memory");
        } else if (ch + 1 < NCH) {
            asm volatile("cp.async.wait_group 1;" ::: "memory");
        } else {
            asm volatile("cp.async.wait_group 0;" ::: "memory");
        }
        __syncthreads();

        int buf = ch % NSTAGE;
        const uint32_t* Ab = smu + buf * STAGE_U32 + g * 1024;
        const uint4*    Bb = (const uint4*)(smu + buf * STAGE_U32 + A_U32);

        uint4 bv[4];
#pragma unroll
        for (int nt = 0; nt < 4; nt++)
            bv[nt] = Bb[(wnb + nt) * 32 + lane];

        if (ch + 4 < NCH) issue(ch + 4);

#pragma unroll
        for (int s = 0; s < 2; s++) {
            uint32_t af[4][4];
#pragma unroll
            for (int mt = 0; mt < 4; mt++) {
                uint4 av = *(const uint4*)(Ab + (s * 4 + mt) * 128 + lane * 4);
                af[mt][0] = av.x; af[mt][1] = av.y; af[mt][2] = av.z; af[mt][3] = av.w;
            }
#pragma unroll
            for (int mt = 0; mt < 4; mt++)
#pragma unroll
                for (int nt = 0; nt < 4; nt++) {
                    uint32_t b0 = s ? bv[nt].z : bv[nt].x;
                    uint32_t b1 = s ? bv[nt].w : bv[nt].y;
                    asm volatile(
                        "mma.sync.aligned.m16n8k16.row.col.f32.f16.f16.f32 "
                        "{%0,%1,%2,%3}, {%4,%5,%6,%7}, {%8,%9}, {%0,%1,%2,%3};"
                        : "+f"(c[mt][nt][0]), "+f"(c[mt][nt][1]),
                          "+f"(c[mt][nt][2]), "+f"(c[mt][nt][3])
                        : "r"(af[mt][0]), "r"(af[mt][1]), "r"(af[mt][2]), "r"(af[mt][3]),
                          "r"(b0), "r"(b1));
                }
        }
    }

    __half* yb = g_yh + (size_t)b * COUT * HW;
#pragma unroll
    for (int mt = 0; mt < 4; mt++) {
        int r0 = oTile + g * 64 + mt * 16 + gid;
        int r1 = r0 + 8;
#pragma unroll
        for (int nt = 0; nt < 4; nt++) {
            int col = pTile + wn + nt * 8 + tg * 2;
            __half2 h0 = __floats2half2_rn(c[mt][nt][0], c[mt][nt][1]);
            __half2 h1 = __floats2half2_rn(c[mt][nt][2], c[mt][nt][3]);
            *(__half2*)(yb + (size_t)r0 * HW + col) = h0;
            *(__half2*)(yb + (size_t)r1 * HW + col) = h1;
        }
    }
}

// ---------------------------------------------------------------------------
// Kernel C: bilinear x2 upsample, STG.128 stores.
// Lane l emits output pixels 4l..4l+3 per row:
//   out[4l+0] = 0.25 v[2l-1] + 0.75 v[2l]
//   out[4l+1] = 0.75 v[2l]   + 0.25 v[2l+1]
//   out[4l+2] = 0.25 v[2l]   + 0.75 v[2l+1]
//   out[4l+3] = 0.75 v[2l+1] + 0.25 v[2l+2]
// (v = vertically-lerped input row, indices clamped to [0,63])
// ---------------------------------------------------------------------------
__global__ __launch_bounds__(256) void upsample_kernel(float* __restrict__ out)
{
    __shared__ float ssm[64 * 68];
    unsigned c = blockIdx.x & 511u;
    unsigned b = blockIdx.x >> 9;
    int tid = threadIdx.x;
    int wid = tid >> 5, lane = tid & 31;

    const uint4* src = (const uint4*)(g_yh + ((size_t)b * COUT + c) * HW);
#pragma unroll
    for (int j = 0; j < 2; j++) {
        int idx = tid + j * 256;
        int row = idx >> 3, col8 = idx & 7;
        uint4 v = __ldg(src + idx);
        float* dst = ssm + row * 68 + col8 * 8;
        float2 f0 = __half22float2(*(__half2*)&v.x);
        float2 f1 = __half22float2(*(__half2*)&v.y);
        float2 f2 = __half22float2(*(__half2*)&v.z);
        float2 f3 = __half22float2(*(__half2*)&v.w);
        dst[0] = f0.x; dst[1] = f0.y; dst[2] = f1.x; dst[3] = f1.y;
        dst[4] = f2.x; dst[5] = f2.y; dst[6] = f3.x; dst[7] = f3.y;
    }
    __syncthreads();

    float* outp = out + ((size_t)b * COUT + c) * OH * OW;
    int xc0 = 2 * lane;
    int xm  = max(0, xc0 - 1);
    int xp  = min(63, xc0 + 2);
#pragma unroll
    for (int i = 0; i < 16; i++) {
        int oy = i * 8 + wid;
        float fy  = oy * 0.5f - 0.25f;
        float y0f = floorf(fy);
        float wy  = fy - y0f;
        int iy0 = max(0, (int)y0f);
        int iy1 = min(63, (int)y0f + 1);
        const float* r0 = ssm + iy0 * 68;
        const float* r1 = ssm + iy1 * 68;

        float vm = r0[xm]      + wy * (r1[xm]      - r0[xm]);
        float v0 = r0[xc0]     + wy * (r1[xc0]     - r0[xc0]);
        float v1 = r0[xc0 + 1] + wy * (r1[xc0 + 1] - r0[xc0 + 1]);
        float vp = r0[xp]      + wy * (r1[xp]      - r0[xp]);

        float4 o;
        o.x = 0.25f * vm + 0.75f * v0;
        o.y = 0.75f * v0 + 0.25f * v1;
        o.z = 0.25f * v0 + 0.75f * v1;
        o.w = 0.75f * v1 + 0.25f * vp;
        *(float4*)(outp + (size_t)oy * OW + 4 * lane) = o;
    }
}

// ---------------------------------------------------------------------------
extern "C" void kernel_launch(void* const* d_in, const int* in_sizes, int n_in,
                              void* d_out, int out_size)
{
    const float* x      = (const float*)d_in[0];
    const float* style  = (const float*)d_in[1];
    const float* conv_w = (const float*)d_in[2];
    const float* mod_w  = (const float*)d_in[3];
    const float* mod_b  = (const float*)d_in[4];
    float* out = (float*)d_out;

    cudaFuncSetAttribute(gemm_mma, cudaFuncAttributeMaxDynamicSharedMemorySize, SM_GEMM_BYTES);

    prep_kernel<<<16512, 256>>>(x, style, conv_w, mod_w, mod_b);

    dim3 ggrid(HW / 128, COUT / 128, B_);   // (32, 4, 16)
    gemm_mma<<<ggrid, 256, SM_GEMM_BYTES>>>();

    upsample_kernel<<<B_ * COUT, 256>>>(out);
}

// round 16
// speedup vs baseline: 1.1034x; 1.1034x over previous
#include <cuda_runtime.h>
#include <cuda_fp16.h>
#include <cstdint>
#include <math.h>

// Problem dims
#define B_    16
#define CIN   512
#define COUT  512
#define H_    64
#define W_    64
#define HW    4096
#define SDIM  32
#define OH    128
#define OW    128
#define EPS   1e-8f

// Scratch
__device__ uint32_t g_wh[(size_t)B_ * COUT * CIN / 2];   // fp16 A-fragment-ordered weights (8 MB)
__device__ uint4    g_xf[(size_t)B_ * 16 * 512 * 32];    // fp16 B-fragment-ordered x (67 MB)
__device__ __half   g_yh[(size_t)B_ * COUT * HW];        // conv output, fp16 (67 MB)

// ---------------------------------------------------------------------------
// Kernel A: fused style modulation + demod + fragment-ordered weight write.
// grid (4 ot, 2 gh, 16 b), 256 threads. (R14 version — measured 10 us)
// ---------------------------------------------------------------------------
__global__ __launch_bounds__(256) void wprep_kernel(
    const float* __restrict__ style,
    const float* __restrict__ conv_w,
    const float* __restrict__ mod_w,
    const float* __restrict__ mod_b)
{
    int ot = blockIdx.x;      // 0..3
    int gh = blockIdx.y;      // 0..1
    int b  = blockIdx.z;      // 0..15
    int tid = threadIdx.x;
    int wid = tid >> 5, lane = tid & 31;
    int gid = lane >> 2, tg = lane & 3;

    __shared__ float s_sh[CIN];
    __shared__ float dm_sh[64];

    const float* st = style + b * SDIM;
#pragma unroll
    for (int rep = 0; rep < 2; rep++) {
        int i = tid + rep * 256;
        float acc = mod_b[i];
        const float* mw = mod_w + i * SDIM;
#pragma unroll
        for (int k = 0; k < SDIM; k++) acc += st[k] * mw[k];
        s_sh[i] = acc;
    }
    __syncthreads();

    int obase = ot * 128 + gh * 64;
#pragma unroll
    for (int cc = 0; cc < 8; cc++) {
        int ol = wid * 8 + cc;
        const float* cw = conv_w + (size_t)(obase + ol) * CIN;
        float sum = 0.f;
#pragma unroll
        for (int it = 0; it < 4; it++) {
            int k4 = lane + it * 32;
            float4 v = __ldg((const float4*)cw + k4);
            int k = k4 * 4;
            float t0 = v.x * s_sh[k], t1 = v.y * s_sh[k + 1];
            float t2 = v.z * s_sh[k + 2], t3 = v.w * s_sh[k + 3];
            sum += t0 * t0 + t1 * t1 + t2 * t2 + t3 * t3;
        }
#pragma unroll
        for (int off = 16; off; off >>= 1)
            sum += __shfl_xor_sync(0xFFFFFFFFu, sum, off);
        if (lane == 0) dm_sh[ol] = rsqrtf(sum + EPS);
    }
    __syncthreads();

    int s  = wid >> 2;
    int mt = wid & 3;
    int fgrp = gh * 8 + wid;
    int o0l = mt * 16 + gid;
    int o1l = o0l + 8;
    int o0 = obase + o0l, o1 = obase + o1l;
    float d0 = dm_sh[o0l];
    float d1 = dm_sh[o1l];

    uint32_t* cb0 = g_wh + ((size_t)((b * 4 + ot) * 16)) * 2048 + fgrp * 128 + lane * 4;
    const float* w0row = conv_w + (size_t)o0 * CIN;
    const float* w1row = conv_w + (size_t)o1 * CIN;

#pragma unroll 4
    for (int c = 0; c < 16; c++) {
        int k0 = c * 32 + s * 16 + tg * 2;
        float s00 = s_sh[k0],     s01 = s_sh[k0 + 1];
        float s08 = s_sh[k0 + 8], s09 = s_sh[k0 + 9];

        float2 w0a = __ldg((const float2*)(w0row + k0));
        float2 w0b = __ldg((const float2*)(w0row + k0 + 8));
        float2 w1a = __ldg((const float2*)(w1row + k0));
        float2 w1b = __ldg((const float2*)(w1row + k0 + 8));

        __half2 h0 = __floats2half2_rn(w0a.x * s00 * d0, w0a.y * s01 * d0);
        __half2 h1 = __floats2half2_rn(w1a.x * s00 * d1, w1a.y * s01 * d1);
        __half2 h2 = __floats2half2_rn(w0b.x * s08 * d0, w0b.y * s09 * d0);
        __half2 h3 = __floats2half2_rn(w1b.x * s08 * d1, w1b.y * s09 * d1);

        uint4 u;
        u.x = *(uint32_t*)&h0; u.y = *(uint32_t*)&h1;
        u.z = *(uint32_t*)&h2; u.w = *(uint32_t*)&h3;
        *(uint4*)(cb0 + (size_t)c * 2048) = u;
    }
}

// ---------------------------------------------------------------------------
// Kernel A3: x -> B-fragment order (R10 direct version — measured fastest).
// ---------------------------------------------------------------------------
__global__ __launch_bounds__(256) void xcvt_kernel(const float* __restrict__ x)
{
    unsigned blk = blockIdx.x;
    unsigned seg = blk & 63u;
    unsigned c   = (blk >> 6) & 15u;
    unsigned b   = blk >> 10;

    unsigned t  = seg * 256u + threadIdx.x;
    unsigned tg = t & 3u;
    unsigned p  = t >> 2;

    const float* xb = x + (size_t)b * CIN * HW + p;
    unsigned rbase = c * 32 + 2 * tg;

    uint4 u;
    {
        float lo = __ldg(xb + (size_t)(rbase + 0) * HW);
        float hi = __ldg(xb + (size_t)(rbase + 1) * HW);
        __half2 h = __floats2half2_rn(lo, hi); u.x = *(uint32_t*)&h;
    }
    {
        float lo = __ldg(xb + (size_t)(rbase + 8) * HW);
        float hi = __ldg(xb + (size_t)(rbase + 9) * HW);
        __half2 h = __floats2half2_rn(lo, hi); u.y = *(uint32_t*)&h;
    }
    {
        float lo = __ldg(xb + (size_t)(rbase + 16) * HW);
        float hi = __ldg(xb + (size_t)(rbase + 17) * HW);
        __half2 h = __floats2half2_rn(lo, hi); u.z = *(uint32_t*)&h;
    }
    {
        float lo = __ldg(xb + (size_t)(rbase + 24) * HW);
        float hi = __ldg(xb + (size_t)(rbase + 25) * HW);
        __half2 h = __floats2half2_rn(lo, hi); u.w = *(uint32_t*)&h;
    }

    unsigned n8 = p >> 3;
    unsigned lane_out = (p & 7u) * 4u + tg;
    g_xf[((size_t)(b * 16 + c) * 512 + n8) * 32 + lane_out] = u;
}

// ---------------------------------------------------------------------------
// Kernel B: batched GEMM, mma.sync.m16n8k16.f16.
// 5-stage cp.async (measured optimum), one sync per chunk:
//   wait 3 -> sync -> bv LDS -> issue(ch+4) -> compute(ch).
// ---------------------------------------------------------------------------
#define A_U32 2048
#define B_U32 2048
#define STAGE_U32 (A_U32 + B_U32)
#define NSTAGE 5
#define SM_GEMM_BYTES (NSTAGE * STAGE_U32 * 4)   // 81920

__device__ __forceinline__ uint32_t smem_u32(const void* p) {
    uint32_t a;
    asm("{ .reg .u64 t; cvta.to.shared.u64 t, %1; cvt.u32.u64 %0, t; }" : "=r"(a) : "l"(p));
    return a;
}

__global__ __launch_bounds__(256, 2) void gemm_mma(void)
{
    extern __shared__ uint32_t smu[];

    int tid = threadIdx.x;
    int wid = tid >> 5, lane = tid & 31;
    int gid = lane >> 2, tg = lane & 3;
    int b = blockIdx.z, oTile = blockIdx.y * 128, pTile = blockIdx.x * 128;
    int g = wid >> 2, wn = (wid & 3) * 32, wnb = (wid & 3) * 4;

    const uint32_t* aglob = g_wh + ((size_t)((b * 4 + blockIdx.y) * 16)) * 2048;
    const uint4*    bglob = g_xf + (size_t)b * 262144 + (size_t)(pTile >> 3) * 32;

    uint32_t sm_u = smem_u32(smu);

    auto issue = [&](int ch) {
        int buf = ch % NSTAGE;
        uint32_t stage = sm_u + buf * STAGE_U32 * 4;
        const uint32_t* as_ = aglob + ch * 2048 + tid * 8;
        uint32_t ad = stage + tid * 32;
        asm volatile("cp.async.cg.shared.global [%0], [%1], 16;" :: "r"(ad),      "l"(as_)     : "memory");
        asm volatile("cp.async.cg.shared.global [%0], [%1], 16;" :: "r"(ad + 16), "l"(as_ + 4) : "memory");
        const uint4* bs_ = bglob + (size_t)ch * 16384 + tid * 2;
        uint32_t bd = stage + A_U32 * 4 + tid * 32;
        asm volatile("cp.async.cg.shared.global [%0], [%1], 16;" :: "r"(bd),      "l"(bs_)     : "memory");
        asm volatile("cp.async.cg.shared.global [%0], [%1], 16;" :: "r"(bd + 16), "l"(bs_ + 1) : "memory");
        asm volatile("cp.async.commit_group;" ::: "memory");
    };

    float c[4][4][4];
#pragma unroll
    for (int mt = 0; mt < 4; mt++)
#pragma unroll
        for (int nt = 0; nt < 4; nt++)
#pragma unroll
            for (int q = 0; q < 4; q++) c[mt][nt][q] = 0.f;

    issue(0); issue(1); issue(2); issue(3);

    const int NCH = CIN / 32;   // 16
    for (int ch = 0; ch < NCH; ch++) {
        if (ch + 3 < NCH) {
            asm volatile("cp.async.wait_group 3;" ::: "memory");
        } else if (ch + 2 < NCH) {
            asm volatile("cp.async.wait_group 2;" ::: "memory");
        } else if (ch + 1 < NCH) {
            asm volatile("cp.async.wait_group 1;" ::: "memory");
        } else {
            asm volatile("cp.async.wait_group 0;" ::: "memory");
        }
        __syncthreads();

        int buf = ch % NSTAGE;
        const uint32_t* Ab = smu + buf * STAGE_U32 + g * 1024;
        const uint4*    Bb = (const uint4*)(smu + buf * STAGE_U32 + A_U32);

        uint4 bv[4];
#pragma unroll
        for (int nt = 0; nt < 4; nt++)
            bv[nt] = Bb[(wnb + nt) * 32 + lane];

        if (ch + 4 < NCH) issue(ch + 4);

#pragma unroll
        for (int s = 0; s < 2; s++) {
            uint32_t af[4][4];
#pragma unroll
            for (int mt = 0; mt < 4; mt++) {
                uint4 av = *(const uint4*)(Ab + (s * 4 + mt) * 128 + lane * 4);
                af[mt][0] = av.x; af[mt][1] = av.y; af[mt][2] = av.z; af[mt][3] = av.w;
            }
#pragma unroll
            for (int mt = 0; mt < 4; mt++)
#pragma unroll
                for (int nt = 0; nt < 4; nt++) {
                    uint32_t b0 = s ? bv[nt].z : bv[nt].x;
                    uint32_t b1 = s ? bv[nt].w : bv[nt].y;
                    asm volatile(
                        "mma.sync.aligned.m16n8k16.row.col.f32.f16.f16.f32 "
                        "{%0,%1,%2,%3}, {%4,%5,%6,%7}, {%8,%9}, {%0,%1,%2,%3};"
                        : "+f"(c[mt][nt][0]), "+f"(c[mt][nt][1]),
                          "+f"(c[mt][nt][2]), "+f"(c[mt][nt][3])
                        : "r"(af[mt][0]), "r"(af[mt][1]), "r"(af[mt][2]), "r"(af[mt][3]),
                          "r"(b0), "r"(b1));
                }
        }
    }

    __half* yb = g_yh + (size_t)b * COUT * HW;
#pragma unroll
    for (int mt = 0; mt < 4; mt++) {
        int r0 = oTile + g * 64 + mt * 16 + gid;
        int r1 = r0 + 8;
#pragma unroll
        for (int nt = 0; nt < 4; nt++) {
            int col = pTile + wn + nt * 8 + tg * 2;
            __half2 h0 = __floats2half2_rn(c[mt][nt][0], c[mt][nt][1]);
            __half2 h1 = __floats2half2_rn(c[mt][nt][2], c[mt][nt][3]);
            *(__half2*)(yb + (size_t)r0 * HW + col) = h0;
            *(__half2*)(yb + (size_t)r1 * HW + col) = h1;
        }
    }
}

// ---------------------------------------------------------------------------
// Kernel C: bilinear x2 upsample, STG.128 stores.
// Lane l emits output pixels 4l..4l+3 per row from 4 vertical lerps.
// ---------------------------------------------------------------------------
__global__ __launch_bounds__(256) void upsample_kernel(float* __restrict__ out)
{
    __shared__ float ssm[64 * 68];
    unsigned c = blockIdx.x & 511u;
    unsigned b = blockIdx.x >> 9;
    int tid = threadIdx.x;
    int wid = tid >> 5, lane = tid & 31;

    const uint4* src = (const uint4*)(g_yh + ((size_t)b * COUT + c) * HW);
#pragma unroll
    for (int j = 0; j < 2; j++) {
        int idx = tid + j * 256;
        int row = idx >> 3, col8 = idx & 7;
        uint4 v = __ldg(src + idx);
        float* dst = ssm + row * 68 + col8 * 8;
        float2 f0 = __half22float2(*(__half2*)&v.x);
        float2 f1 = __half22float2(*(__half2*)&v.y);
        float2 f2 = __half22float2(*(__half2*)&v.z);
        float2 f3 = __half22float2(*(__half2*)&v.w);
        dst[0] = f0.x; dst[1] = f0.y; dst[2] = f1.x; dst[3] = f1.y;
        dst[4] = f2.x; dst[5] = f2.y; dst[6] = f3.x; dst[7] = f3.y;
    }
    __syncthreads();

    float* outp = out + ((size_t)b * COUT + c) * OH * OW;
    int xc0 = 2 * lane;
    int xm  = max(0, xc0 - 1);
    int xp  = min(63, xc0 + 2);
#pragma unroll
    for (int i = 0; i < 16; i++) {
        int oy = i * 8 + wid;
        float fy  = oy * 0.5f - 0.25f;
        float y0f = floorf(fy);
        float wy  = fy - y0f;
        int iy0 = max(0, (int)y0f);
        int iy1 = min(63, (int)y0f + 1);
        const float* r0 = ssm + iy0 * 68;
        const float* r1 = ssm + iy1 * 68;

        float vm = r0[xm]      + wy * (r1[xm]      - r0[xm]);
        float v0 = r0[xc0]     + wy * (r1[xc0]     - r0[xc0]);
        float v1 = r0[xc0 + 1] + wy * (r1[xc0 + 1] - r0[xc0 + 1]);
        float vp = r0[xp]      + wy * (r1[xp]      - r0[xp]);

        float4 o;
        o.x = 0.25f * vm + 0.75f * v0;
        o.y = 0.75f * v0 + 0.25f * v1;
        o.z = 0.25f * v0 + 0.75f * v1;
        o.w = 0.75f * v1 + 0.25f * vp;
        *(float4*)(outp + (size_t)oy * OW + 4 * lane) = o;
    }
}

// ---------------------------------------------------------------------------
extern "C" void kernel_launch(void* const* d_in, const int* in_sizes, int n_in,
                              void* d_out, int out_size)
{
    const float* x      = (const float*)d_in[0];
    const float* style  = (const float*)d_in[1];
    const float* conv_w = (const float*)d_in[2];
    const float* mod_w  = (const float*)d_in[3];
    const float* mod_b  = (const float*)d_in[4];
    float* out = (float*)d_out;

    cudaFuncSetAttribute(gemm_mma, cudaFuncAttributeMaxDynamicSharedMemorySize, SM_GEMM_BYTES);

    dim3 wgrid(4, 2, 16);
    wprep_kernel<<<wgrid, 256>>>(style, conv_w, mod_w, mod_b);

    xcvt_kernel<<<16384, 256>>>(x);

    dim3 ggrid(HW / 128, COUT / 128, B_);   // (32, 4, 16)
    gemm_mma<<<ggrid, 256, SM_GEMM_BYTES>>>();

    upsample_kernel<<<B_ * COUT, 256>>>(out);
}

// round 17
// speedup vs baseline: 1.1062x; 1.0025x over previous
#include <cuda_runtime.h>
#include <cuda_fp16.h>
#include <cstdint>
#include <math.h>

// Problem dims
#define B_    16
#define CIN   512
#define COUT  512
#define H_    64
#define W_    64
#define HW    4096
#define SDIM  32
#define OH    128
#define OW    128
#define EPS   1e-8f

// Scratch
__device__ uint32_t g_wh[(size_t)B_ * COUT * CIN / 2];   // fp16 A-fragment-ordered weights (8 MB)
__device__ uint4    g_xf[(size_t)B_ * 16 * 512 * 32];    // fp16 B-fragment-ordered x (67 MB)
__device__ __half   g_yh[(size_t)B_ * COUT * HW];        // conv output, fp16 (67 MB)

// ---------------------------------------------------------------------------
// Kernel A: fused style modulation + demod + fragment-ordered weight write.
// grid (4 ot, 2 gh, 16 b), 256 threads.
// ---------------------------------------------------------------------------
__global__ __launch_bounds__(256) void wprep_kernel(
    const float* __restrict__ style,
    const float* __restrict__ conv_w,
    const float* __restrict__ mod_w,
    const float* __restrict__ mod_b)
{
    int ot = blockIdx.x;      // 0..3
    int gh = blockIdx.y;      // 0..1
    int b  = blockIdx.z;      // 0..15
    int tid = threadIdx.x;
    int wid = tid >> 5, lane = tid & 31;
    int gid = lane >> 2, tg = lane & 3;

    __shared__ float s_sh[CIN];
    __shared__ float dm_sh[64];

    const float* st = style + b * SDIM;
#pragma unroll
    for (int rep = 0; rep < 2; rep++) {
        int i = tid + rep * 256;
        float acc = mod_b[i];
        const float* mw = mod_w + i * SDIM;
#pragma unroll
        for (int k = 0; k < SDIM; k++) acc += st[k] * mw[k];
        s_sh[i] = acc;
    }
    __syncthreads();

    int obase = ot * 128 + gh * 64;
#pragma unroll
    for (int cc = 0; cc < 8; cc++) {
        int ol = wid * 8 + cc;
        const float* cw = conv_w + (size_t)(obase + ol) * CIN;
        float sum = 0.f;
#pragma unroll
        for (int it = 0; it < 4; it++) {
            int k4 = lane + it * 32;
            float4 v = __ldg((const float4*)cw + k4);
            int k = k4 * 4;
            float t0 = v.x * s_sh[k], t1 = v.y * s_sh[k + 1];
            float t2 = v.z * s_sh[k + 2], t3 = v.w * s_sh[k + 3];
            sum += t0 * t0 + t1 * t1 + t2 * t2 + t3 * t3;
        }
#pragma unroll
        for (int off = 16; off; off >>= 1)
            sum += __shfl_xor_sync(0xFFFFFFFFu, sum, off);
        if (lane == 0) dm_sh[ol] = rsqrtf(sum + EPS);
    }
    __syncthreads();

    int s  = wid >> 2;
    int mt = wid & 3;
    int fgrp = gh * 8 + wid;
    int o0l = mt * 16 + gid;
    int o1l = o0l + 8;
    int o0 = obase + o0l, o1 = obase + o1l;
    float d0 = dm_sh[o0l];
    float d1 = dm_sh[o1l];

    uint32_t* cb0 = g_wh + ((size_t)((b * 4 + ot) * 16)) * 2048 + fgrp * 128 + lane * 4;
    const float* w0row = conv_w + (size_t)o0 * CIN;
    const float* w1row = conv_w + (size_t)o1 * CIN;

#pragma unroll 4
    for (int c = 0; c < 16; c++) {
        int k0 = c * 32 + s * 16 + tg * 2;
        float s00 = s_sh[k0],     s01 = s_sh[k0 + 1];
        float s08 = s_sh[k0 + 8], s09 = s_sh[k0 + 9];

        float2 w0a = __ldg((const float2*)(w0row + k0));
        float2 w0b = __ldg((const float2*)(w0row + k0 + 8));
        float2 w1a = __ldg((const float2*)(w1row + k0));
        float2 w1b = __ldg((const float2*)(w1row + k0 + 8));

        __half2 h0 = __floats2half2_rn(w0a.x * s00 * d0, w0a.y * s01 * d0);
        __half2 h1 = __floats2half2_rn(w1a.x * s00 * d1, w1a.y * s01 * d1);
        __half2 h2 = __floats2half2_rn(w0b.x * s08 * d0, w0b.y * s09 * d0);
        __half2 h3 = __floats2half2_rn(w1b.x * s08 * d1, w1b.y * s09 * d1);

        uint4 u;
        u.x = *(uint32_t*)&h0; u.y = *(uint32_t*)&h1;
        u.z = *(uint32_t*)&h2; u.w = *(uint32_t*)&h3;
        *(uint4*)(cb0 + (size_t)c * 2048) = u;
    }
}

// ---------------------------------------------------------------------------
// Kernel A3: x -> B-fragment order (R10 direct version — measured fastest).
// ---------------------------------------------------------------------------
__global__ __launch_bounds__(256) void xcvt_kernel(const float* __restrict__ x)
{
    unsigned blk = blockIdx.x;
    unsigned seg = blk & 63u;
    unsigned c   = (blk >> 6) & 15u;
    unsigned b   = blk >> 10;

    unsigned t  = seg * 256u + threadIdx.x;
    unsigned tg = t & 3u;
    unsigned p  = t >> 2;

    const float* xb = x + (size_t)b * CIN * HW + p;
    unsigned rbase = c * 32 + 2 * tg;

    uint4 u;
    {
        float lo = __ldg(xb + (size_t)(rbase + 0) * HW);
        float hi = __ldg(xb + (size_t)(rbase + 1) * HW);
        __half2 h = __floats2half2_rn(lo, hi); u.x = *(uint32_t*)&h;
    }
    {
        float lo = __ldg(xb + (size_t)(rbase + 8) * HW);
        float hi = __ldg(xb + (size_t)(rbase + 9) * HW);
        __half2 h = __floats2half2_rn(lo, hi); u.y = *(uint32_t*)&h;
    }
    {
        float lo = __ldg(xb + (size_t)(rbase + 16) * HW);
        float hi = __ldg(xb + (size_t)(rbase + 17) * HW);
        __half2 h = __floats2half2_rn(lo, hi); u.z = *(uint32_t*)&h;
    }
    {
        float lo = __ldg(xb + (size_t)(rbase + 24) * HW);
        float hi = __ldg(xb + (size_t)(rbase + 25) * HW);
        __half2 h = __floats2half2_rn(lo, hi); u.w = *(uint32_t*)&h;
    }

    unsigned n8 = p >> 3;
    unsigned lane_out = (p & 7u) * 4u + tg;
    g_xf[((size_t)(b * 16 + c) * 512 + n8) * 32 + lane_out] = u;
}

// ---------------------------------------------------------------------------
// Kernel B: batched GEMM, mma.sync.m16n8k16.f16.
// 5-stage cp.async (measured optimum), one sync per chunk:
//   wait 3 -> sync -> bv LDS -> issue(ch+4) -> compute(ch).
// ---------------------------------------------------------------------------
#define A_U32 2048
#define B_U32 2048
#define STAGE_U32 (A_U32 + B_U32)
#define NSTAGE 5
#define SM_GEMM_BYTES (NSTAGE * STAGE_U32 * 4)   // 81920

__device__ __forceinline__ uint32_t smem_u32(const void* p) {
    uint32_t a;
    asm("{ .reg .u64 t; cvta.to.shared.u64 t, %1; cvt.u32.u64 %0, t; }" : "=r"(a) : "l"(p));
    return a;
}

__global__ __launch_bounds__(256, 2) void gemm_mma(void)
{
    extern __shared__ uint32_t smu[];

    int tid = threadIdx.x;
    int wid = tid >> 5, lane = tid & 31;
    int gid = lane >> 2, tg = lane & 3;
    int b = blockIdx.z, oTile = blockIdx.y * 128, pTile = blockIdx.x * 128;
    int g = wid >> 2, wn = (wid & 3) * 32, wnb = (wid & 3) * 4;

    const uint32_t* aglob = g_wh + ((size_t)((b * 4 + blockIdx.y) * 16)) * 2048;
    const uint4*    bglob = g_xf + (size_t)b * 262144 + (size_t)(pTile >> 3) * 32;

    uint32_t sm_u = smem_u32(smu);

    auto issue = [&](int ch) {
        int buf = ch % NSTAGE;
        uint32_t stage = sm_u + buf * STAGE_U32 * 4;
        const uint32_t* as_ = aglob + ch * 2048 + tid * 8;
        uint32_t ad = stage + tid * 32;
        asm volatile("cp.async.cg.shared.global [%0], [%1], 16;" :: "r"(ad),      "l"(as_)     : "memory");
        asm volatile("cp.async.cg.shared.global [%0], [%1], 16;" :: "r"(ad + 16), "l"(as_ + 4) : "memory");
        const uint4* bs_ = bglob + (size_t)ch * 16384 + tid * 2;
        uint32_t bd = stage + A_U32 * 4 + tid * 32;
        asm volatile("cp.async.cg.shared.global [%0], [%1], 16;" :: "r"(bd),      "l"(bs_)     : "memory");
        asm volatile("cp.async.cg.shared.global [%0], [%1], 16;" :: "r"(bd + 16), "l"(bs_ + 1) : "memory");
        asm volatile("cp.async.commit_group;" ::: "memory");
    };

    float c[4][4][4];
#pragma unroll
    for (int mt = 0; mt < 4; mt++)
#pragma unroll
        for (int nt = 0; nt < 4; nt++)
#pragma unroll
            for (int q = 0; q < 4; q++) c[mt][nt][q] = 0.f;

    issue(0); issue(1); issue(2); issue(3);

    const int NCH = CIN / 32;   // 16
    for (int ch = 0; ch < NCH; ch++) {
        if (ch + 3 < NCH) {
            asm volatile("cp.async.wait_group 3;" ::: "memory");
        } else if (ch + 2 < NCH) {
            asm volatile("cp.async.wait_group 2;" ::: "memory");
        } else if (ch + 1 < NCH) {
            asm volatile("cp.async.wait_group 1;" ::: "memory");
        } else {
            asm volatile("cp.async.wait_group 0;" ::: "memory");
        }
        __syncthreads();

        int buf = ch % NSTAGE;
        const uint32_t* Ab = smu + buf * STAGE_U32 + g * 1024;
        const uint4*    Bb = (const uint4*)(smu + buf * STAGE_U32 + A_U32);

        uint4 bv[4];
#pragma unroll
        for (int nt = 0; nt < 4; nt++)
            bv[nt] = Bb[(wnb + nt) * 32 + lane];

        if (ch + 4 < NCH) issue(ch + 4);

#pragma unroll
        for (int s = 0; s < 2; s++) {
            uint32_t af[4][4];
#pragma unroll
            for (int mt = 0; mt < 4; mt++) {
                uint4 av = *(const uint4*)(Ab + (s * 4 + mt) * 128 + lane * 4);
                af[mt][0] = av.x; af[mt][1] = av.y; af[mt][2] = av.z; af[mt][3] = av.w;
            }
#pragma unroll
            for (int mt = 0; mt < 4; mt++)
#pragma unroll
                for (int nt = 0; nt < 4; nt++) {
                    uint32_t b0 = s ? bv[nt].z : bv[nt].x;
                    uint32_t b1 = s ? bv[nt].w : bv[nt].y;
                    asm volatile(
                        "mma.sync.aligned.m16n8k16.row.col.f32.f16.f16.f32 "
                        "{%0,%1,%2,%3}, {%4,%5,%6,%7}, {%8,%9}, {%0,%1,%2,%3};"
                        : "+f"(c[mt][nt][0]), "+f"(c[mt][nt][1]),
                          "+f"(c[mt][nt][2]), "+f"(c[mt][nt][3])
                        : "r"(af[mt][0]), "r"(af[mt][1]), "r"(af[mt][2]), "r"(af[mt][3]),
                          "r"(b0), "r"(b1));
                }
        }
    }

    __half* yb = g_yh + (size_t)b * COUT * HW;
#pragma unroll
    for (int mt = 0; mt < 4; mt++) {
        int r0 = oTile + g * 64 + mt * 16 + gid;
        int r1 = r0 + 8;
#pragma unroll
        for (int nt = 0; nt < 4; nt++) {
            int col = pTile + wn + nt * 8 + tg * 2;
            __half2 h0 = __floats2half2_rn(c[mt][nt][0], c[mt][nt][1]);
            __half2 h1 = __floats2half2_rn(c[mt][nt][2], c[mt][nt][3]);
            *(__half2*)(yb + (size_t)r0 * HW + col) = h0;
            *(__half2*)(yb + (size_t)r1 * HW + col) = h1;
        }
    }
}

// ---------------------------------------------------------------------------
// Kernel C: bilinear x2 upsample, STG.128 + streaming (evict-first) stores.
// Output is write-once — .cs keeps it from evicting g_yh (67 MB, L2-resident
// after GEMM) so the upsample reads hit L2 instead of DRAM.
// ---------------------------------------------------------------------------
__global__ __launch_bounds__(256) void upsample_kernel(float* __restrict__ out)
{
    __shared__ float ssm[64 * 68];
    unsigned c = blockIdx.x & 511u;
    unsigned b = blockIdx.x >> 9;
    int tid = threadIdx.x;
    int wid = tid >> 5, lane = tid & 31;

    const uint4* src = (const uint4*)(g_yh + ((size_t)b * COUT + c) * HW);
#pragma unroll
    for (int j = 0; j < 2; j++) {
        int idx = tid + j * 256;
        int row = idx >> 3, col8 = idx & 7;
        uint4 v = __ldg(src + idx);
        float* dst = ssm + row * 68 + col8 * 8;
        float2 f0 = __half22float2(*(__half2*)&v.x);
        float2 f1 = __half22float2(*(__half2*)&v.y);
        float2 f2 = __half22float2(*(__half2*)&v.z);
        float2 f3 = __half22float2(*(__half2*)&v.w);
        dst[0] = f0.x; dst[1] = f0.y; dst[2] = f1.x; dst[3] = f1.y;
        dst[4] = f2.x; dst[5] = f2.y; dst[6] = f3.x; dst[7] = f3.y;
    }
    __syncthreads();

    float* outp = out + ((size_t)b * COUT + c) * OH * OW;
    int xc0 = 2 * lane;
    int xm  = max(0, xc0 - 1);
    int xp  = min(63, xc0 + 2);
#pragma unroll
    for (int i = 0; i < 16; i++) {
        int oy = i * 8 + wid;
        float fy  = oy * 0.5f - 0.25f;
        float y0f = floorf(fy);
        float wy  = fy - y0f;
        int iy0 = max(0, (int)y0f);
        int iy1 = min(63, (int)y0f + 1);
        const float* r0 = ssm + iy0 * 68;
        const float* r1 = ssm + iy1 * 68;

        float vm = r0[xm]      + wy * (r1[xm]      - r0[xm]);
        float v0 = r0[xc0]     + wy * (r1[xc0]     - r0[xc0]);
        float v1 = r0[xc0 + 1] + wy * (r1[xc0 + 1] - r0[xc0 + 1]);
        float vp = r0[xp]      + wy * (r1[xp]      - r0[xp]);

        float4 o;
        o.x = 0.25f * vm + 0.75f * v0;
        o.y = 0.75f * v0 + 0.25f * v1;
        o.z = 0.25f * v0 + 0.75f * v1;
        o.w = 0.75f * v1 + 0.25f * vp;
        __stcs((float4*)(outp + (size_t)oy * OW + 4 * lane), o);
    }
}

// ---------------------------------------------------------------------------
extern "C" void kernel_launch(void* const* d_in, const int* in_sizes, int n_in,
                              void* d_out, int out_size)
{
    const float* x      = (const float*)d_in[0];
    const float* style  = (const float*)d_in[1];
    const float* conv_w = (const float*)d_in[2];
    const float* mod_w  = (const float*)d_in[3];
    const float* mod_b  = (const float*)d_in[4];
    float* out = (float*)d_out;

    cudaFuncSetAttribute(gemm_mma, cudaFuncAttributeMaxDynamicSharedMemorySize, SM_GEMM_BYTES);

    dim3 wgrid(4, 2, 16);
    wprep_kernel<<<wgrid, 256>>>(style, conv_w, mod_w, mod_b);

    xcvt_kernel<<<16384, 256>>>(x);

    dim3 ggrid(HW / 128, COUT / 128, B_);   // (32, 4, 16)
    gemm_mma<<<ggrid, 256, SM_GEMM_BYTES>>>();

    upsample_kernel<<<B_ * COUT, 256>>>(out);
}